// round 15
// baseline (speedup 1.0000x reference)
#include <cuda_runtime.h>
#include <cuda_bf16.h>
#include <math.h>
#include <stdint.h>

#define BATCH 4
#define SEQ   512
#define TOKS  (BATCH*SEQ)
#define DH    1600
#define NHEADS 50
#define PH    32
#define NREL  100

__device__ __nv_bfloat16 g_hh[TOKS*DH], g_hl[TOKS*DH];
__device__ __nv_bfloat16 g_qh[TOKS*DH], g_ql[TOKS*DH];
__device__ __nv_bfloat16 g_kh[TOKS*DH], g_kl[TOKS*DH];
__device__ __nv_bfloat16 g_vh[TOKS*DH], g_vl[TOKS*DH];
__device__ __nv_bfloat16 g_ch[TOKS*DH], g_cl[TOKS*DH];
__device__ __nv_bfloat16 g_ah[TOKS*DH], g_al[TOKS*DH];
__device__ __nv_bfloat16 g_1h[TOKS*DH], g_1l[TOKS*DH];
__device__ __nv_bfloat16 g_Wh[6][DH*DH];
__device__ __nv_bfloat16 g_Wl[6][DH*DH];

__global__ __launch_bounds__(256) void convert_weight6(
    const float* W0, const float* W1, const float* W2,
    const float* W3, const float* W4, const float* W5,
    __nv_bfloat16* __restrict__ hi_base, __nv_bfloat16* __restrict__ lo_base)
{
    __shared__ float t[32][33];
    const int wi = blockIdx.z;
    const float* W = (wi == 0) ? W0 : (wi == 1) ? W1 : (wi == 2) ? W2 :
                     (wi == 3) ? W3 : (wi == 4) ? W4 : W5;
    __nv_bfloat16* hi = hi_base + (size_t)wi * DH * DH;
    __nv_bfloat16* lo = lo_base + (size_t)wi * DH * DH;
    const int n0 = blockIdx.x * 32, k0 = blockIdx.y * 32;
    const int tx = threadIdx.x, ty = threadIdx.y;
    #pragma unroll
    for (int j = 0; j < 32; j += 8)
        t[ty + j][tx] = W[(size_t)(k0 + ty + j) * DH + n0 + tx];
    __syncthreads();
    #pragma unroll
    for (int j = 0; j < 32; j += 8) {
        float v = t[tx][ty + j];
        __nv_bfloat16 h = __float2bfloat16(v);
        __nv_bfloat16 l = __float2bfloat16(v - __bfloat162float(h));
        size_t o = (size_t)(n0 + ty + j) * DH + k0 + tx;
        hi[o] = h; lo[o] = l;
    }
}

__global__ __launch_bounds__(256) void split_act(
    const float* __restrict__ x,
    __nv_bfloat16* __restrict__ hi, __nv_bfloat16* __restrict__ lo)
{
    size_t i = ((size_t)blockIdx.x * 256 + threadIdx.x) * 4;
    float4 v = *(const float4*)(x + i);
    __nv_bfloat16 hx = __float2bfloat16(v.x), hy = __float2bfloat16(v.y);
    __nv_bfloat16 hz = __float2bfloat16(v.z), hw = __float2bfloat16(v.w);
    __nv_bfloat162 h01; h01.x = hx; h01.y = hy;
    __nv_bfloat162 h23; h23.x = hz; h23.y = hw;
    *(__nv_bfloat162*)(hi + i)     = h01;
    *(__nv_bfloat162*)(hi + i + 2) = h23;
    __nv_bfloat162 l01, l23;
    l01.x = __float2bfloat16(v.x - __bfloat162float(hx));
    l01.y = __float2bfloat16(v.y - __bfloat162float(hy));
    l23.x = __float2bfloat16(v.z - __bfloat162float(hz));
    l23.y = __float2bfloat16(v.w - __bfloat162float(hw));
    *(__nv_bfloat162*)(lo + i)     = l01;
    *(__nv_bfloat162*)(lo + i + 2) = l23;
}

#define GSTAGE 8320
#define GSMEM  (2 * GSTAGE * 4)

__device__ __forceinline__ void mma16816(float* c, const uint32_t* a,
                                         uint32_t b0, uint32_t b1) {
    asm volatile(
        "mma.sync.aligned.m16n8k16.row.col.f32.bf16.bf16.f32 "
        "{%0,%1,%2,%3}, {%4,%5,%6,%7}, {%8,%9}, {%0,%1,%2,%3};"
        : "+f"(c[0]), "+f"(c[1]), "+f"(c[2]), "+f"(c[3])
        : "r"(a[0]), "r"(a[1]), "r"(a[2]), "r"(a[3]), "r"(b0), "r"(b1));
}
__device__ __forceinline__ void cpasync16(uint32_t dst, const void* src) {
    asm volatile("cp.async.cg.shared.global [%0], [%1], 16;"
                 :: "r"(dst), "l"(src));
}
__device__ __forceinline__ void ldsm4(uint32_t* r, uint32_t a) {
    asm volatile("ldmatrix.sync.aligned.m8n8.x4.shared.b16 {%0,%1,%2,%3}, [%4];"
                 : "=r"(r[0]), "=r"(r[1]), "=r"(r[2]), "=r"(r[3]) : "r"(a));
}
__device__ __forceinline__ void ldsm2t(uint32_t* r, uint32_t a) {
    asm volatile("ldmatrix.sync.aligned.m8n8.x2.trans.shared.b16 {%0,%1}, [%2];"
                 : "=r"(r[0]), "=r"(r[1]) : "r"(a));
}
__device__ __forceinline__ uint32_t packbf(__nv_bfloat16 a, __nv_bfloat16 b) {
    return (uint32_t)__bfloat16_as_ushort(a) |
           ((uint32_t)__bfloat16_as_ushort(b) << 16);
}

// regs capped for 3 CTAs/SM (24 warps): single wave for grid=320, more
// latency hiding. B fragments loaded in-loop (keeps reg count <= 85).
__global__ __launch_bounds__(256, 3) void hgemm_v5(
    const __nv_bfloat16* __restrict__ Ah, const __nv_bfloat16* __restrict__ Al,
    const __nv_bfloat16* __restrict__ Bh, const __nv_bfloat16* __restrict__ Bl,
    const float* __restrict__ bias,
    float* __restrict__ Cf,
    __nv_bfloat16* __restrict__ Ch, __nv_bfloat16* __restrict__ Cl,
    int act, int mode)
{
    extern __shared__ uint32_t smw[];
    const uint32_t sm0 = (uint32_t)__cvta_generic_to_shared(smw);
    const int tid  = threadIdx.x;
    const int lane = tid & 31, warp = tid >> 5;
    const int wm = warp >> 1, wn = warp & 1;
    const int g = lane >> 2, t4 = lane & 3;
    const int bm = blockIdx.y * 128, bn = blockIdx.x * 80;

    float acc[2][5][4];
    #pragma unroll
    for (int mt = 0; mt < 2; ++mt)
        #pragma unroll
        for (int nt = 0; nt < 5; ++nt)
            #pragma unroll
            for (int i = 0; i < 4; ++i) acc[mt][nt][i] = 0.f;

    const uint32_t aRow = wm * 32 + (lane & 7) + 8 * ((lane >> 3) & 1);
    const uint32_t aOff = (aRow * 20 + 4 * (lane >> 4)) * 4;
    const uint32_t bOff = (5120 + (wn * 40 + (lane & 7)) * 20 + 4 * (lane >> 3)) * 4;

    auto load_tile = [&](int stage, int kk) {
        uint32_t sb = sm0 + stage * GSTAGE * 4;
        #pragma unroll
        for (int it = 0; it < 4; ++it) {
            int idx = tid + it * 256;
            int hl = idx >> 9, r = (idx >> 2) & 127, c = idx & 3;
            const __nv_bfloat16* src =
                (hl ? Al : Ah) + (size_t)(bm + r) * DH + kk + c * 8;
            cpasync16(sb + (hl * 2560 + r * 20 + c * 4) * 4, src);
        }
        for (int idx = tid; idx < 640; idx += 256) {
            int hl = idx >= 320;
            int j  = idx - hl * 320;
            int r  = j >> 2, c = j & 3;
            const __nv_bfloat16* src =
                (hl ? Bl : Bh) + (size_t)(bn + r) * DH + kk + c * 8;
            cpasync16(sb + (5120 + hl * 1600 + r * 20 + c * 4) * 4, src);
        }
        asm volatile("cp.async.commit_group;");
    };

    const int NT = DH / 32;
    load_tile(0, 0);
    for (int t = 0; t < NT; ++t) {
        int cur = t & 1;
        if (t + 1 < NT) {
            load_tile(cur ^ 1, (t + 1) * 32);
            asm volatile("cp.async.wait_group 1;");
        } else {
            asm volatile("cp.async.wait_group 0;");
        }
        __syncthreads();
        const uint32_t sb = sm0 + cur * GSTAGE * 4;
        #pragma unroll
        for (int kh = 0; kh < 2; ++kh) {
            const int ks = kh * 8, o = kh * 2;
            uint32_t ah[2][4], al[2][4];
            #pragma unroll
            for (int mt = 0; mt < 2; ++mt) {
                uint32_t a = sb + aOff + (mt * 320 + ks) * 4;
                ldsm4(ah[mt], a);
                ldsm4(al[mt], a + 10240);
            }
            #pragma unroll
            for (int nt = 0; nt < 5; ++nt) {
                uint32_t bh[4], bl[4];
                ldsm4(bh, sb + bOff + nt * 640);
                ldsm4(bl, sb + bOff + nt * 640 + 6400);
                #pragma unroll
                for (int mt = 0; mt < 2; ++mt) {
                    mma16816(acc[mt][nt], ah[mt], bh[o], bh[o + 1]);
                    mma16816(acc[mt][nt], ah[mt], bl[o], bl[o + 1]);
                    mma16816(acc[mt][nt], al[mt], bh[o], bh[o + 1]);
                }
            }
        }
        __syncthreads();
    }
    #pragma unroll
    for (int mt = 0; mt < 2; ++mt) {
        #pragma unroll
        for (int nt = 0; nt < 5; ++nt) {
            int r0 = bm + wm * 32 + mt * 16 + g;
            int c0 = bn + wn * 40 + nt * 8 + t4 * 2;
            float b0v = bias[c0], b1v = bias[c0 + 1];
            float x0 = acc[mt][nt][0] + b0v, x1 = acc[mt][nt][1] + b1v;
            float x2 = acc[mt][nt][2] + b0v, x3 = acc[mt][nt][3] + b1v;
            if (act) {
                x0 = 0.5f * x0 * (1.f + erff(x0 * 0.70710678118654752f));
                x1 = 0.5f * x1 * (1.f + erff(x1 * 0.70710678118654752f));
                x2 = 0.5f * x2 * (1.f + erff(x2 * 0.70710678118654752f));
                x3 = 0.5f * x3 * (1.f + erff(x3 * 0.70710678118654752f));
            }
            if (mode == 0) {
                *(float2*)(Cf + (size_t)r0 * DH + c0)       = make_float2(x0, x1);
                *(float2*)(Cf + (size_t)(r0 + 8) * DH + c0) = make_float2(x2, x3);
            } else {
                __nv_bfloat162 h01, h23, l01, l23;
                h01.x = __float2bfloat16(x0); h01.y = __float2bfloat16(x1);
                h23.x = __float2bfloat16(x2); h23.y = __float2bfloat16(x3);
                l01.x = __float2bfloat16(x0 - __bfloat162float(h01.x));
                l01.y = __float2bfloat16(x1 - __bfloat162float(h01.y));
                l23.x = __float2bfloat16(x2 - __bfloat162float(h23.x));
                l23.y = __float2bfloat16(x3 - __bfloat162float(h23.y));
                *(__nv_bfloat162*)(Ch + (size_t)r0 * DH + c0)       = h01;
                *(__nv_bfloat162*)(Ch + (size_t)(r0 + 8) * DH + c0) = h23;
                *(__nv_bfloat162*)(Cl + (size_t)r0 * DH + c0)       = l01;
                *(__nv_bfloat162*)(Cl + (size_t)(r0 + 8) * DH + c0) = l23;
            }
        }
    }
}

// ---- tensor-core attention (identical to passing R13) ----
#define ASMEM (23780 * 4)

__global__ __launch_bounds__(128, 2) void attn_mma(
    const __nv_bfloat16* __restrict__ Qh, const __nv_bfloat16* __restrict__ Ql,
    const __nv_bfloat16* __restrict__ Kh, const __nv_bfloat16* __restrict__ Kl,
    const __nv_bfloat16* __restrict__ Vh, const __nv_bfloat16* __restrict__ Vl,
    const float* __restrict__ relk, const float* __restrict__ relv,
    const int* __restrict__ rm,
    __nv_bfloat16* __restrict__ ctxh, __nv_bfloat16* __restrict__ ctxl)
{
    extern __shared__ uint32_t sw[];
    const uint32_t s0 = (uint32_t)__cvta_generic_to_shared(sw);
    float* sf = (float*)sw;
    const int tid = threadIdx.x;
    const int w = tid >> 5, lane = tid & 31;
    const int g = lane >> 2, t4 = lane & 3;
    const int b = blockIdx.x / NHEADS, h = blockIdx.x % NHEADS;
    const int qbase = blockIdx.y * 64;
    const float scale = 0.1767766952966369f;

    #pragma unroll
    for (int it = 0; it < 4; ++it) {
        int idx = tid + it * 128;
        int hl = idx >> 8, r = (idx >> 2) & 63, c = idx & 3;
        cpasync16(s0 + (hl * 1280 + r * 20 + c * 4) * 4,
                  (hl ? Ql : Qh) + (size_t)(b * SEQ + qbase + r) * DH + h * PH + c * 8);
    }
    asm volatile("cp.async.commit_group;");
    for (int i = tid; i < 3200; i += 128)
        sf[20480 + (i >> 5) * 33 + (i & 31)] = relv[i];
    for (int i = tid; i < 6400; i += 128) sf[14080 + i] = 0.f;
    asm volatile("cp.async.wait_group 0;");
    __syncthreads();

    {
        int q = tid >> 1, rh = (tid & 1) * 50;
        const __nv_bfloat16* sb = (const __nv_bfloat16*)sw;
        float qv[32];
        #pragma unroll
        for (int d = 0; d < 32; ++d)
            qv[d] = __bfloat162float(sb[q * 40 + d]) +
                    __bfloat162float(sb[2560 + q * 40 + d]);
        for (int r = rh; r < rh + 50; ++r) {
            float a = 0.f;
            #pragma unroll
            for (int d = 0; d < 32; ++d) a = fmaf(qv[d], relk[r * 32 + d], a);
            sf[7680 + q * 100 + r] = a;
        }
    }

    const uint32_t aBase = s0 + ((16 * w + (lane & 7) + 8 * ((lane >> 3) & 1)) * 20
                                + 4 * (lane >> 4)) * 4;
    const uint32_t kBase = s0 + (2560 + (lane & 7) * 20 + 4 * (lane >> 3)) * 4;
    const int vRow = lane & 15;

    float oacc[4][4];
    #pragma unroll
    for (int nd = 0; nd < 4; ++nd)
        #pragma unroll
        for (int i = 0; i < 4; ++i) oacc[nd][i] = 0.f;
    float lg = 0.f, lg8 = 0.f;
    const int rowg = qbase + 16 * w + g;
    const int* rmg  = rm + ((size_t)(b * SEQ + rowg)) * SEQ;
    const int* rmg8 = rmg + 8 * SEQ;
    const float* qrl_g  = sf + 7680 + (16 * w + g) * 100;
    const float* qrl_g8 = qrl_g + 800;
    float* msg  = sf + 14080 + (16 * w + g) * 100;
    float* msg8 = msg + 800;

    for (int ti = 0; ti < 8; ++ti) {
        __syncthreads();
        #pragma unroll
        for (int it = 0; it < 8; ++it) {
            int idx = tid + it * 128;
            int arr = idx >> 8, r = (idx >> 2) & 63, c = idx & 3;
            const __nv_bfloat16* base = arr == 0 ? Kh : arr == 1 ? Kl :
                                        arr == 2 ? Vh : Vl;
            cpasync16(s0 + (2560 + arr * 1280 + r * 20 + c * 4) * 4,
                      base + (size_t)(b * SEQ + ti * 64 + r) * DH + h * PH + c * 8);
        }
        asm volatile("cp.async.commit_group;");
        asm volatile("cp.async.wait_group 0;");
        __syncthreads();

        float sacc[8][4];
        #pragma unroll
        for (int n = 0; n < 8; ++n)
            #pragma unroll
            for (int i = 0; i < 4; ++i) sacc[n][i] = 0.f;
        uint32_t qf[2][4], qfl[2][4];
        #pragma unroll
        for (int kh = 0; kh < 2; ++kh) {
            ldsm4(qf[kh],  aBase + kh * 32);
            ldsm4(qfl[kh], aBase + kh * 32 + 5120);
        }
        #pragma unroll
        for (int ng = 0; ng < 2; ++ng) {
            uint32_t kb[4][4], kl_[4][4];
            #pragma unroll
            for (int j = 0; j < 4; ++j) {
                ldsm4(kb[j],  kBase + (ng * 4 + j) * 640);
                ldsm4(kl_[j], kBase + (ng * 4 + j) * 640 + 5120);
            }
            #pragma unroll
            for (int kh = 0; kh < 2; ++kh) {
                const int o = kh * 2;
                #pragma unroll
                for (int j = 0; j < 4; ++j)
                    mma16816(sacc[ng*4+j], qf[kh],  kb[j][o],  kb[j][o+1]);
                #pragma unroll
                for (int j = 0; j < 4; ++j)
                    mma16816(sacc[ng*4+j], qf[kh],  kl_[j][o], kl_[j][o+1]);
                #pragma unroll
                for (int j = 0; j < 4; ++j)
                    mma16816(sacc[ng*4+j], qfl[kh], kb[j][o],  kb[j][o+1]);
            }
        }

        uint32_t ph[8][2], pl[8][2];
        #pragma unroll
        for (int n = 0; n < 8; ++n) {
            int k0 = ti * 64 + n * 8 + 2 * t4;
            int2 r2  = *(const int2*)&rmg[k0];
            int2 r28 = *(const int2*)&rmg8[k0];
            float p0 = __expf((sacc[n][0] + qrl_g[r2.x])   * scale);
            float p1 = __expf((sacc[n][1] + qrl_g[r2.y])   * scale);
            float p2 = __expf((sacc[n][2] + qrl_g8[r28.x]) * scale);
            float p3 = __expf((sacc[n][3] + qrl_g8[r28.y]) * scale);
            lg += p0 + p1; lg8 += p2 + p3;
            atomicAdd(&msg[r2.x],   p0);
            atomicAdd(&msg[r2.y],   p1);
            atomicAdd(&msg8[r28.x], p2);
            atomicAdd(&msg8[r28.y], p3);
            __nv_bfloat16 h0 = __float2bfloat16(p0), h1 = __float2bfloat16(p1);
            __nv_bfloat16 h2 = __float2bfloat16(p2), h3 = __float2bfloat16(p3);
            ph[n][0] = packbf(h0, h1); ph[n][1] = packbf(h2, h3);
            pl[n][0] = packbf(__float2bfloat16(p0 - __bfloat162float(h0)),
                              __float2bfloat16(p1 - __bfloat162float(h1)));
            pl[n][1] = packbf(__float2bfloat16(p2 - __bfloat162float(h2)),
                              __float2bfloat16(p3 - __bfloat162float(h3)));
        }

        #pragma unroll
        for (int kc = 0; kc < 4; ++kc) {
            uint32_t pa[4]  = { ph[2*kc][0], ph[2*kc][1], ph[2*kc+1][0], ph[2*kc+1][1] };
            uint32_t pal[4] = { pl[2*kc][0], pl[2*kc][1], pl[2*kc+1][0], pl[2*kc+1][1] };
            uint32_t vb[4][2], vl2[4][2];
            #pragma unroll
            for (int nd = 0; nd < 4; ++nd) {
                uint32_t va = s0 + (5120 + (16 * kc + vRow) * 20 + nd * 4) * 4;
                ldsm2t(vb[nd],  va);
                ldsm2t(vl2[nd], va + 5120);
            }
            #pragma unroll
            for (int nd = 0; nd < 4; ++nd)
                mma16816(oacc[nd], pa,  vb[nd][0],  vb[nd][1]);
            #pragma unroll
            for (int nd = 0; nd < 4; ++nd)
                mma16816(oacc[nd], pa,  vl2[nd][0], vl2[nd][1]);
            #pragma unroll
            for (int nd = 0; nd < 4; ++nd)
                mma16816(oacc[nd], pal, vb[nd][0],  vb[nd][1]);
        }
    }

    lg  += __shfl_xor_sync(0xffffffffu, lg, 1);
    lg  += __shfl_xor_sync(0xffffffffu, lg, 2);
    lg8 += __shfl_xor_sync(0xffffffffu, lg8, 1);
    lg8 += __shfl_xor_sync(0xffffffffu, lg8, 2);
    __syncthreads();

    float ag[8], ag8[8];
    #pragma unroll
    for (int i = 0; i < 8; ++i) { ag[i] = 0.f; ag8[i] = 0.f; }
    for (int r = 0; r < NREL; ++r) {
        float mg = msg[r], mg8 = msg8[r];
        const float* rv = sf + 20480 + r * 33;
        #pragma unroll
        for (int nd = 0; nd < 4; ++nd) {
            #pragma unroll
            for (int e = 0; e < 2; ++e) {
                float rvv = rv[nd * 8 + 2 * t4 + e];
                ag[nd * 2 + e]  = fmaf(mg,  rvv, ag[nd * 2 + e]);
                ag8[nd * 2 + e] = fmaf(mg8, rvv, ag8[nd * 2 + e]);
            }
        }
    }
    float ig = 1.f / lg, ig8 = 1.f / lg8;
    size_t og  = (size_t)(b * SEQ + rowg) * DH + h * PH;
    size_t og8 = og + 8 * DH;
    #pragma unroll
    for (int nd = 0; nd < 4; ++nd) {
        int d0 = nd * 8 + 2 * t4;
        float v0 = (oacc[nd][0] + ag[nd*2])    * ig;
        float v1 = (oacc[nd][1] + ag[nd*2+1])  * ig;
        float v2 = (oacc[nd][2] + ag8[nd*2])   * ig8;
        float v3 = (oacc[nd][3] + ag8[nd*2+1]) * ig8;
        __nv_bfloat162 hA, hB, lA, lB;
        hA.x = __float2bfloat16(v0); hA.y = __float2bfloat16(v1);
        hB.x = __float2bfloat16(v2); hB.y = __float2bfloat16(v3);
        lA.x = __float2bfloat16(v0 - __bfloat162float(hA.x));
        lA.y = __float2bfloat16(v1 - __bfloat162float(hA.y));
        lB.x = __float2bfloat16(v2 - __bfloat162float(hB.x));
        lB.y = __float2bfloat16(v3 - __bfloat162float(hB.y));
        *(__nv_bfloat162*)(ctxh + og  + d0) = hA;
        *(__nv_bfloat162*)(ctxh + og8 + d0) = hB;
        *(__nv_bfloat162*)(ctxl + og  + d0) = lA;
        *(__nv_bfloat162*)(ctxl + og8 + d0) = lB;
    }
}

extern "C" void kernel_launch(void* const* d_in, const int* in_sizes, int n_in,
                              void* d_out, int out_size)
{
    const float* hidden = (const float*)d_in[0];
    const float* Wq = (const float*)d_in[1];
    const float* bq = (const float*)d_in[2];
    const float* Wk = (const float*)d_in[3];
    const float* bk = (const float*)d_in[4];
    const float* Wv = (const float*)d_in[5];
    const float* bv = (const float*)d_in[6];
    const float* Wo = (const float*)d_in[7];
    const float* bo = (const float*)d_in[8];
    const float* rke = (const float*)d_in[9];
    const float* rve = (const float*)d_in[10];
    const float* W1 = (const float*)d_in[11];
    const float* b1 = (const float*)d_in[12];
    const float* W2 = (const float*)d_in[13];
    const float* b2 = (const float*)d_in[14];
    const int*   rm = (const int*)d_in[15];
    float* out = (float*)d_out;

    __nv_bfloat16 *hh, *hl, *qh, *ql, *kh, *kl, *vh, *vl;
    __nv_bfloat16 *ch, *cl, *ah, *al, *h1h, *h1l, *Wh, *Wl;
    cudaGetSymbolAddress((void**)&hh, g_hh);  cudaGetSymbolAddress((void**)&hl, g_hl);
    cudaGetSymbolAddress((void**)&qh, g_qh);  cudaGetSymbolAddress((void**)&ql, g_ql);
    cudaGetSymbolAddress((void**)&kh, g_kh);  cudaGetSymbolAddress((void**)&kl, g_kl);
    cudaGetSymbolAddress((void**)&vh, g_vh);  cudaGetSymbolAddress((void**)&vl, g_vl);
    cudaGetSymbolAddress((void**)&ch, g_ch);  cudaGetSymbolAddress((void**)&cl, g_cl);
    cudaGetSymbolAddress((void**)&ah, g_ah);  cudaGetSymbolAddress((void**)&al, g_al);
    cudaGetSymbolAddress((void**)&h1h, g_1h); cudaGetSymbolAddress((void**)&h1l, g_1l);
    cudaGetSymbolAddress((void**)&Wh, g_Wh);  cudaGetSymbolAddress((void**)&Wl, g_Wl);

    cudaFuncSetAttribute(hgemm_v5,
        cudaFuncAttributeMaxDynamicSharedMemorySize, GSMEM);
    cudaFuncSetAttribute(attn_mma,
        cudaFuncAttributeMaxDynamicSharedMemorySize, ASMEM);

    dim3 cb(32, 8), cg(DH / 32, DH / 32, 6);
    convert_weight6<<<cg, cb>>>(Wq, Wk, Wv, Wo, W1, W2, Wh, Wl);
    split_act<<<(TOKS * DH) / (256 * 4), 256>>>(hidden, hh, hl);

    size_t WW = (size_t)DH * DH;
    dim3 gg(DH / 80, TOKS / 128);

    hgemm_v5<<<gg, 256, GSMEM>>>(hh, hl, Wh + 0 * WW, Wl + 0 * WW, bq,
                                 nullptr, qh, ql, 0, 1);
    hgemm_v5<<<gg, 256, GSMEM>>>(hh, hl, Wh + 1 * WW, Wl + 1 * WW, bk,
                                 nullptr, kh, kl, 0, 1);
    hgemm_v5<<<gg, 256, GSMEM>>>(hh, hl, Wh + 2 * WW, Wl + 2 * WW, bv,
                                 nullptr, vh, vl, 0, 1);

    dim3 ag(BATCH * NHEADS, SEQ / 64);   // (200, 8)
    attn_mma<<<ag, 128, ASMEM>>>(qh, ql, kh, kl, vh, vl, rke, rve, rm, ch, cl);

    hgemm_v5<<<gg, 256, GSMEM>>>(ch, cl, Wh + 3 * WW, Wl + 3 * WW, bo,
                                 nullptr, ah, al, 0, 1);
    hgemm_v5<<<gg, 256, GSMEM>>>(ah, al, Wh + 4 * WW, Wl + 4 * WW, b1,
                                 nullptr, h1h, h1l, 1, 1);
    hgemm_v5<<<gg, 256, GSMEM>>>(h1h, h1l, Wh + 5 * WW, Wl + 5 * WW, b2,
                                 out, nullptr, nullptr, 0, 0);
}

// round 16
// speedup vs baseline: 1.2324x; 1.2324x over previous
#include <cuda_runtime.h>
#include <cuda_bf16.h>
#include <math.h>
#include <stdint.h>

#define BATCH 4
#define SEQ   512
#define TOKS  (BATCH*SEQ)
#define DH    1600
#define NHEADS 50
#define PH    32
#define NREL  100

__device__ __nv_bfloat16 g_hh[TOKS*DH], g_hl[TOKS*DH];
__device__ __nv_bfloat16 g_qh[TOKS*DH], g_ql[TOKS*DH];
__device__ __nv_bfloat16 g_kh[TOKS*DH], g_kl[TOKS*DH];
__device__ __nv_bfloat16 g_vh[TOKS*DH], g_vl[TOKS*DH];
__device__ __nv_bfloat16 g_ch[TOKS*DH], g_cl[TOKS*DH];
__device__ __nv_bfloat16 g_ah[TOKS*DH], g_al[TOKS*DH];
__device__ __nv_bfloat16 g_1h[TOKS*DH], g_1l[TOKS*DH];
__device__ __nv_bfloat16 g_Wh[6][DH*DH];
__device__ __nv_bfloat16 g_Wl[6][DH*DH];

__global__ __launch_bounds__(256) void convert_weight6(
    const float* W0, const float* W1, const float* W2,
    const float* W3, const float* W4, const float* W5,
    __nv_bfloat16* __restrict__ hi_base, __nv_bfloat16* __restrict__ lo_base)
{
    __shared__ float t[32][33];
    const int wi = blockIdx.z;
    const float* W = (wi == 0) ? W0 : (wi == 1) ? W1 : (wi == 2) ? W2 :
                     (wi == 3) ? W3 : (wi == 4) ? W4 : W5;
    __nv_bfloat16* hi = hi_base + (size_t)wi * DH * DH;
    __nv_bfloat16* lo = lo_base + (size_t)wi * DH * DH;
    const int n0 = blockIdx.x * 32, k0 = blockIdx.y * 32;
    const int tx = threadIdx.x, ty = threadIdx.y;
    #pragma unroll
    for (int j = 0; j < 32; j += 8)
        t[ty + j][tx] = W[(size_t)(k0 + ty + j) * DH + n0 + tx];
    __syncthreads();
    #pragma unroll
    for (int j = 0; j < 32; j += 8) {
        float v = t[tx][ty + j];
        __nv_bfloat16 h = __float2bfloat16(v);
        __nv_bfloat16 l = __float2bfloat16(v - __bfloat162float(h));
        size_t o = (size_t)(n0 + ty + j) * DH + k0 + tx;
        hi[o] = h; lo[o] = l;
    }
}

__global__ __launch_bounds__(256) void split_act(
    const float* __restrict__ x,
    __nv_bfloat16* __restrict__ hi, __nv_bfloat16* __restrict__ lo)
{
    size_t i = ((size_t)blockIdx.x * 256 + threadIdx.x) * 4;
    float4 v = *(const float4*)(x + i);
    __nv_bfloat16 hx = __float2bfloat16(v.x), hy = __float2bfloat16(v.y);
    __nv_bfloat16 hz = __float2bfloat16(v.z), hw = __float2bfloat16(v.w);
    __nv_bfloat162 h01; h01.x = hx; h01.y = hy;
    __nv_bfloat162 h23; h23.x = hz; h23.y = hw;
    *(__nv_bfloat162*)(hi + i)     = h01;
    *(__nv_bfloat162*)(hi + i + 2) = h23;
    __nv_bfloat162 l01, l23;
    l01.x = __float2bfloat16(v.x - __bfloat162float(hx));
    l01.y = __float2bfloat16(v.y - __bfloat162float(hy));
    l23.x = __float2bfloat16(v.z - __bfloat162float(hz));
    l23.y = __float2bfloat16(v.w - __bfloat162float(hw));
    *(__nv_bfloat162*)(lo + i)     = l01;
    *(__nv_bfloat162*)(lo + i + 2) = l23;
}

#define GSTAGE 8320
#define GSMEM  (2 * GSTAGE * 4)

__device__ __forceinline__ void mma16816(float* c, const uint32_t* a,
                                         uint32_t b0, uint32_t b1) {
    asm volatile(
        "mma.sync.aligned.m16n8k16.row.col.f32.bf16.bf16.f32 "
        "{%0,%1,%2,%3}, {%4,%5,%6,%7}, {%8,%9}, {%0,%1,%2,%3};"
        : "+f"(c[0]), "+f"(c[1]), "+f"(c[2]), "+f"(c[3])
        : "r"(a[0]), "r"(a[1]), "r"(a[2]), "r"(a[3]), "r"(b0), "r"(b1));
}
__device__ __forceinline__ void cpasync16(uint32_t dst, const void* src) {
    asm volatile("cp.async.cg.shared.global [%0], [%1], 16;"
                 :: "r"(dst), "l"(src));
}
__device__ __forceinline__ void ldsm4(uint32_t* r, uint32_t a) {
    asm volatile("ldmatrix.sync.aligned.m8n8.x4.shared.b16 {%0,%1,%2,%3}, [%4];"
                 : "=r"(r[0]), "=r"(r[1]), "=r"(r[2]), "=r"(r[3]) : "r"(a));
}
__device__ __forceinline__ void ldsm2t(uint32_t* r, uint32_t a) {
    asm volatile("ldmatrix.sync.aligned.m8n8.x2.trans.shared.b16 {%0,%1}, [%2];"
                 : "=r"(r[0]), "=r"(r[1]) : "r"(a));
}
__device__ __forceinline__ uint32_t packbf(__nv_bfloat16 a, __nv_bfloat16 b) {
    return (uint32_t)__bfloat16_as_ushort(a) |
           ((uint32_t)__bfloat16_as_ushort(b) << 16);
}

// 128 threads (4 warps, warp = 32 rows x 80 cols), 3 CTAs/SM by smem:
// grid 320 <= 444 slots -> SINGLE WAVE. Tile/layout identical to v4.
__global__ __launch_bounds__(128, 3) void hgemm_v6(
    const __nv_bfloat16* __restrict__ Ah, const __nv_bfloat16* __restrict__ Al,
    const __nv_bfloat16* __restrict__ Bh, const __nv_bfloat16* __restrict__ Bl,
    const float* __restrict__ bias,
    float* __restrict__ Cf,
    __nv_bfloat16* __restrict__ Ch, __nv_bfloat16* __restrict__ Cl,
    int act, int mode)
{
    extern __shared__ uint32_t smw[];
    const uint32_t sm0 = (uint32_t)__cvta_generic_to_shared(smw);
    const int tid  = threadIdx.x;
    const int lane = tid & 31, warp = tid >> 5;   // 0..3 = m-slice
    const int g = lane >> 2, t4 = lane & 3;
    const int bm = blockIdx.y * 128, bn = blockIdx.x * 80;

    float acc[2][10][4];
    #pragma unroll
    for (int mt = 0; mt < 2; ++mt)
        #pragma unroll
        for (int nt = 0; nt < 10; ++nt)
            #pragma unroll
            for (int i = 0; i < 4; ++i) acc[mt][nt][i] = 0.f;

    const uint32_t aRow = warp * 32 + (lane & 7) + 8 * ((lane >> 3) & 1);
    const uint32_t aOff = (aRow * 20 + 4 * (lane >> 4)) * 4;
    const uint32_t bOff = (5120 + (lane & 7) * 20 + 4 * (lane >> 3)) * 4;

    auto load_tile = [&](int stage, int kk) {
        uint32_t sb = sm0 + stage * GSTAGE * 4;
        #pragma unroll
        for (int it = 0; it < 8; ++it) {          // A: 1024 16B chunks
            int idx = tid + it * 128;
            int hl = idx >> 9, r = (idx >> 2) & 127, c = idx & 3;
            const __nv_bfloat16* src =
                (hl ? Al : Ah) + (size_t)(bm + r) * DH + kk + c * 8;
            cpasync16(sb + (hl * 2560 + r * 20 + c * 4) * 4, src);
        }
        #pragma unroll
        for (int it = 0; it < 5; ++it) {          // B: 640 chunks
            int idx = tid + it * 128;
            int hl = idx >= 320;
            int j  = idx - hl * 320;
            int r  = j >> 2, c = j & 3;
            const __nv_bfloat16* src =
                (hl ? Bl : Bh) + (size_t)(bn + r) * DH + kk + c * 8;
            cpasync16(sb + (5120 + hl * 1600 + r * 20 + c * 4) * 4, src);
        }
        asm volatile("cp.async.commit_group;");
    };

    const int NT = DH / 32;
    load_tile(0, 0);
    for (int t = 0; t < NT; ++t) {
        int cur = t & 1;
        if (t + 1 < NT) {
            load_tile(cur ^ 1, (t + 1) * 32);
            asm volatile("cp.async.wait_group 1;");
        } else {
            asm volatile("cp.async.wait_group 0;");
        }
        __syncthreads();
        const uint32_t sb = sm0 + cur * GSTAGE * 4;
        #pragma unroll
        for (int kh = 0; kh < 2; ++kh) {
            const int ks = kh * 8, o = kh * 2;
            uint32_t ah[2][4], al[2][4];
            #pragma unroll
            for (int mt = 0; mt < 2; ++mt) {
                uint32_t a = sb + aOff + (mt * 320 + ks) * 4;
                ldsm4(ah[mt], a);
                ldsm4(al[mt], a + 10240);
            }
            #pragma unroll
            for (int nt = 0; nt < 10; ++nt) {
                uint32_t bh[4], bl[4];
                ldsm4(bh, sb + bOff + nt * 640);
                ldsm4(bl, sb + bOff + nt * 640 + 6400);
                #pragma unroll
                for (int mt = 0; mt < 2; ++mt) {
                    mma16816(acc[mt][nt], ah[mt], bh[o], bh[o + 1]);
                    mma16816(acc[mt][nt], ah[mt], bl[o], bl[o + 1]);
                    mma16816(acc[mt][nt], al[mt], bh[o], bh[o + 1]);
                }
            }
        }
        __syncthreads();
    }
    #pragma unroll
    for (int mt = 0; mt < 2; ++mt) {
        #pragma unroll
        for (int nt = 0; nt < 10; ++nt) {
            int r0 = bm + warp * 32 + mt * 16 + g;
            int c0 = bn + nt * 8 + t4 * 2;
            float b0v = bias[c0], b1v = bias[c0 + 1];
            float x0 = acc[mt][nt][0] + b0v, x1 = acc[mt][nt][1] + b1v;
            float x2 = acc[mt][nt][2] + b0v, x3 = acc[mt][nt][3] + b1v;
            if (act) {
                x0 = 0.5f * x0 * (1.f + erff(x0 * 0.70710678118654752f));
                x1 = 0.5f * x1 * (1.f + erff(x1 * 0.70710678118654752f));
                x2 = 0.5f * x2 * (1.f + erff(x2 * 0.70710678118654752f));
                x3 = 0.5f * x3 * (1.f + erff(x3 * 0.70710678118654752f));
            }
            if (mode == 0) {
                *(float2*)(Cf + (size_t)r0 * DH + c0)       = make_float2(x0, x1);
                *(float2*)(Cf + (size_t)(r0 + 8) * DH + c0) = make_float2(x2, x3);
            } else {
                __nv_bfloat162 h01, h23, l01, l23;
                h01.x = __float2bfloat16(x0); h01.y = __float2bfloat16(x1);
                h23.x = __float2bfloat16(x2); h23.y = __float2bfloat16(x3);
                l01.x = __float2bfloat16(x0 - __bfloat162float(h01.x));
                l01.y = __float2bfloat16(x1 - __bfloat162float(h01.y));
                l23.x = __float2bfloat16(x2 - __bfloat162float(h23.x));
                l23.y = __float2bfloat16(x3 - __bfloat162float(h23.y));
                *(__nv_bfloat162*)(Ch + (size_t)r0 * DH + c0)       = h01;
                *(__nv_bfloat162*)(Ch + (size_t)(r0 + 8) * DH + c0) = h23;
                *(__nv_bfloat162*)(Cl + (size_t)r0 * DH + c0)       = l01;
                *(__nv_bfloat162*)(Cl + (size_t)(r0 + 8) * DH + c0) = l23;
            }
        }
    }
}

// ---- tensor-core attention (identical to passing R13/R14) ----
#define ASMEM (23780 * 4)

__global__ __launch_bounds__(128, 2) void attn_mma(
    const __nv_bfloat16* __restrict__ Qh, const __nv_bfloat16* __restrict__ Ql,
    const __nv_bfloat16* __restrict__ Kh, const __nv_bfloat16* __restrict__ Kl,
    const __nv_bfloat16* __restrict__ Vh, const __nv_bfloat16* __restrict__ Vl,
    const float* __restrict__ relk, const float* __restrict__ relv,
    const int* __restrict__ rm,
    __nv_bfloat16* __restrict__ ctxh, __nv_bfloat16* __restrict__ ctxl)
{
    extern __shared__ uint32_t sw[];
    const uint32_t s0 = (uint32_t)__cvta_generic_to_shared(sw);
    float* sf = (float*)sw;
    const int tid = threadIdx.x;
    const int w = tid >> 5, lane = tid & 31;
    const int g = lane >> 2, t4 = lane & 3;
    const int b = blockIdx.x / NHEADS, h = blockIdx.x % NHEADS;
    const int qbase = blockIdx.y * 64;
    const float scale = 0.1767766952966369f;

    #pragma unroll
    for (int it = 0; it < 4; ++it) {
        int idx = tid + it * 128;
        int hl = idx >> 8, r = (idx >> 2) & 63, c = idx & 3;
        cpasync16(s0 + (hl * 1280 + r * 20 + c * 4) * 4,
                  (hl ? Ql : Qh) + (size_t)(b * SEQ + qbase + r) * DH + h * PH + c * 8);
    }
    asm volatile("cp.async.commit_group;");
    for (int i = tid; i < 3200; i += 128)
        sf[20480 + (i >> 5) * 33 + (i & 31)] = relv[i];
    for (int i = tid; i < 6400; i += 128) sf[14080 + i] = 0.f;
    asm volatile("cp.async.wait_group 0;");
    __syncthreads();

    {
        int q = tid >> 1, rh = (tid & 1) * 50;
        const __nv_bfloat16* sb = (const __nv_bfloat16*)sw;
        float qv[32];
        #pragma unroll
        for (int d = 0; d < 32; ++d)
            qv[d] = __bfloat162float(sb[q * 40 + d]) +
                    __bfloat162float(sb[2560 + q * 40 + d]);
        for (int r = rh; r < rh + 50; ++r) {
            float a = 0.f;
            #pragma unroll
            for (int d = 0; d < 32; ++d) a = fmaf(qv[d], relk[r * 32 + d], a);
            sf[7680 + q * 100 + r] = a;
        }
    }

    const uint32_t aBase = s0 + ((16 * w + (lane & 7) + 8 * ((lane >> 3) & 1)) * 20
                                + 4 * (lane >> 4)) * 4;
    const uint32_t kBase = s0 + (2560 + (lane & 7) * 20 + 4 * (lane >> 3)) * 4;
    const int vRow = lane & 15;

    float oacc[4][4];
    #pragma unroll
    for (int nd = 0; nd < 4; ++nd)
        #pragma unroll
        for (int i = 0; i < 4; ++i) oacc[nd][i] = 0.f;
    float lg = 0.f, lg8 = 0.f;
    const int rowg = qbase + 16 * w + g;
    const int* rmg  = rm + ((size_t)(b * SEQ + rowg)) * SEQ;
    const int* rmg8 = rmg + 8 * SEQ;
    const float* qrl_g  = sf + 7680 + (16 * w + g) * 100;
    const float* qrl_g8 = qrl_g + 800;
    float* msg  = sf + 14080 + (16 * w + g) * 100;
    float* msg8 = msg + 800;

    for (int ti = 0; ti < 8; ++ti) {
        __syncthreads();
        #pragma unroll
        for (int it = 0; it < 8; ++it) {
            int idx = tid + it * 128;
            int arr = idx >> 8, r = (idx >> 2) & 63, c = idx & 3;
            const __nv_bfloat16* base = arr == 0 ? Kh : arr == 1 ? Kl :
                                        arr == 2 ? Vh : Vl;
            cpasync16(s0 + (2560 + arr * 1280 + r * 20 + c * 4) * 4,
                      base + (size_t)(b * SEQ + ti * 64 + r) * DH + h * PH + c * 8);
        }
        asm volatile("cp.async.commit_group;");
        asm volatile("cp.async.wait_group 0;");
        __syncthreads();

        float sacc[8][4];
        #pragma unroll
        for (int n = 0; n < 8; ++n)
            #pragma unroll
            for (int i = 0; i < 4; ++i) sacc[n][i] = 0.f;
        uint32_t qf[2][4], qfl[2][4];
        #pragma unroll
        for (int kh = 0; kh < 2; ++kh) {
            ldsm4(qf[kh],  aBase + kh * 32);
            ldsm4(qfl[kh], aBase + kh * 32 + 5120);
        }
        #pragma unroll
        for (int ng = 0; ng < 2; ++ng) {
            uint32_t kb[4][4], kl_[4][4];
            #pragma unroll
            for (int j = 0; j < 4; ++j) {
                ldsm4(kb[j],  kBase + (ng * 4 + j) * 640);
                ldsm4(kl_[j], kBase + (ng * 4 + j) * 640 + 5120);
            }
            #pragma unroll
            for (int kh = 0; kh < 2; ++kh) {
                const int o = kh * 2;
                #pragma unroll
                for (int j = 0; j < 4; ++j)
                    mma16816(sacc[ng*4+j], qf[kh],  kb[j][o],  kb[j][o+1]);
                #pragma unroll
                for (int j = 0; j < 4; ++j)
                    mma16816(sacc[ng*4+j], qf[kh],  kl_[j][o], kl_[j][o+1]);
                #pragma unroll
                for (int j = 0; j < 4; ++j)
                    mma16816(sacc[ng*4+j], qfl[kh], kb[j][o],  kb[j][o+1]);
            }
        }

        uint32_t ph[8][2], pl[8][2];
        #pragma unroll
        for (int n = 0; n < 8; ++n) {
            int k0 = ti * 64 + n * 8 + 2 * t4;
            int2 r2  = *(const int2*)&rmg[k0];
            int2 r28 = *(const int2*)&rmg8[k0];
            float p0 = __expf((sacc[n][0] + qrl_g[r2.x])   * scale);
            float p1 = __expf((sacc[n][1] + qrl_g[r2.y])   * scale);
            float p2 = __expf((sacc[n][2] + qrl_g8[r28.x]) * scale);
            float p3 = __expf((sacc[n][3] + qrl_g8[r28.y]) * scale);
            lg += p0 + p1; lg8 += p2 + p3;
            atomicAdd(&msg[r2.x],   p0);
            atomicAdd(&msg[r2.y],   p1);
            atomicAdd(&msg8[r28.x], p2);
            atomicAdd(&msg8[r28.y], p3);
            __nv_bfloat16 h0 = __float2bfloat16(p0), h1 = __float2bfloat16(p1);
            __nv_bfloat16 h2 = __float2bfloat16(p2), h3 = __float2bfloat16(p3);
            ph[n][0] = packbf(h0, h1); ph[n][1] = packbf(h2, h3);
            pl[n][0] = packbf(__float2bfloat16(p0 - __bfloat162float(h0)),
                              __float2bfloat16(p1 - __bfloat162float(h1)));
            pl[n][1] = packbf(__float2bfloat16(p2 - __bfloat162float(h2)),
                              __float2bfloat16(p3 - __bfloat162float(h3)));
        }

        #pragma unroll
        for (int kc = 0; kc < 4; ++kc) {
            uint32_t pa[4]  = { ph[2*kc][0], ph[2*kc][1], ph[2*kc+1][0], ph[2*kc+1][1] };
            uint32_t pal[4] = { pl[2*kc][0], pl[2*kc][1], pl[2*kc+1][0], pl[2*kc+1][1] };
            uint32_t vb[4][2], vl2[4][2];
            #pragma unroll
            for (int nd = 0; nd < 4; ++nd) {
                uint32_t va = s0 + (5120 + (16 * kc + vRow) * 20 + nd * 4) * 4;
                ldsm2t(vb[nd],  va);
                ldsm2t(vl2[nd], va + 5120);
            }
            #pragma unroll
            for (int nd = 0; nd < 4; ++nd)
                mma16816(oacc[nd], pa,  vb[nd][0],  vb[nd][1]);
            #pragma unroll
            for (int nd = 0; nd < 4; ++nd)
                mma16816(oacc[nd], pa,  vl2[nd][0], vl2[nd][1]);
            #pragma unroll
            for (int nd = 0; nd < 4; ++nd)
                mma16816(oacc[nd], pal, vb[nd][0],  vb[nd][1]);
        }
    }

    lg  += __shfl_xor_sync(0xffffffffu, lg, 1);
    lg  += __shfl_xor_sync(0xffffffffu, lg, 2);
    lg8 += __shfl_xor_sync(0xffffffffu, lg8, 1);
    lg8 += __shfl_xor_sync(0xffffffffu, lg8, 2);
    __syncthreads();

    float ag[8], ag8[8];
    #pragma unroll
    for (int i = 0; i < 8; ++i) { ag[i] = 0.f; ag8[i] = 0.f; }
    for (int r = 0; r < NREL; ++r) {
        float mg = msg[r], mg8 = msg8[r];
        const float* rv = sf + 20480 + r * 33;
        #pragma unroll
        for (int nd = 0; nd < 4; ++nd) {
            #pragma unroll
            for (int e = 0; e < 2; ++e) {
                float rvv = rv[nd * 8 + 2 * t4 + e];
                ag[nd * 2 + e]  = fmaf(mg,  rvv, ag[nd * 2 + e]);
                ag8[nd * 2 + e] = fmaf(mg8, rvv, ag8[nd * 2 + e]);
            }
        }
    }
    float ig = 1.f / lg, ig8 = 1.f / lg8;
    size_t og  = (size_t)(b * SEQ + rowg) * DH + h * PH;
    size_t og8 = og + 8 * DH;
    #pragma unroll
    for (int nd = 0; nd < 4; ++nd) {
        int d0 = nd * 8 + 2 * t4;
        float v0 = (oacc[nd][0] + ag[nd*2])    * ig;
        float v1 = (oacc[nd][1] + ag[nd*2+1])  * ig;
        float v2 = (oacc[nd][2] + ag8[nd*2])   * ig8;
        float v3 = (oacc[nd][3] + ag8[nd*2+1]) * ig8;
        __nv_bfloat162 hA, hB, lA, lB;
        hA.x = __float2bfloat16(v0); hA.y = __float2bfloat16(v1);
        hB.x = __float2bfloat16(v2); hB.y = __float2bfloat16(v3);
        lA.x = __float2bfloat16(v0 - __bfloat162float(hA.x));
        lA.y = __float2bfloat16(v1 - __bfloat162float(hA.y));
        lB.x = __float2bfloat16(v2 - __bfloat162float(hB.x));
        lB.y = __float2bfloat16(v3 - __bfloat162float(hB.y));
        *(__nv_bfloat162*)(ctxh + og  + d0) = hA;
        *(__nv_bfloat162*)(ctxh + og8 + d0) = hB;
        *(__nv_bfloat162*)(ctxl + og  + d0) = lA;
        *(__nv_bfloat162*)(ctxl + og8 + d0) = lB;
    }
}

extern "C" void kernel_launch(void* const* d_in, const int* in_sizes, int n_in,
                              void* d_out, int out_size)
{
    const float* hidden = (const float*)d_in[0];
    const float* Wq = (const float*)d_in[1];
    const float* bq = (const float*)d_in[2];
    const float* Wk = (const float*)d_in[3];
    const float* bk = (const float*)d_in[4];
    const float* Wv = (const float*)d_in[5];
    const float* bv = (const float*)d_in[6];
    const float* Wo = (const float*)d_in[7];
    const float* bo = (const float*)d_in[8];
    const float* rke = (const float*)d_in[9];
    const float* rve = (const float*)d_in[10];
    const float* W1 = (const float*)d_in[11];
    const float* b1 = (const float*)d_in[12];
    const float* W2 = (const float*)d_in[13];
    const float* b2 = (const float*)d_in[14];
    const int*   rm = (const int*)d_in[15];
    float* out = (float*)d_out;

    __nv_bfloat16 *hh, *hl, *qh, *ql, *kh, *kl, *vh, *vl;
    __nv_bfloat16 *ch, *cl, *ah, *al, *h1h, *h1l, *Wh, *Wl;
    cudaGetSymbolAddress((void**)&hh, g_hh);  cudaGetSymbolAddress((void**)&hl, g_hl);
    cudaGetSymbolAddress((void**)&qh, g_qh);  cudaGetSymbolAddress((void**)&ql, g_ql);
    cudaGetSymbolAddress((void**)&kh, g_kh);  cudaGetSymbolAddress((void**)&kl, g_kl);
    cudaGetSymbolAddress((void**)&vh, g_vh);  cudaGetSymbolAddress((void**)&vl, g_vl);
    cudaGetSymbolAddress((void**)&ch, g_ch);  cudaGetSymbolAddress((void**)&cl, g_cl);
    cudaGetSymbolAddress((void**)&ah, g_ah);  cudaGetSymbolAddress((void**)&al, g_al);
    cudaGetSymbolAddress((void**)&h1h, g_1h); cudaGetSymbolAddress((void**)&h1l, g_1l);
    cudaGetSymbolAddress((void**)&Wh, g_Wh);  cudaGetSymbolAddress((void**)&Wl, g_Wl);

    cudaFuncSetAttribute(hgemm_v6,
        cudaFuncAttributeMaxDynamicSharedMemorySize, GSMEM);
    cudaFuncSetAttribute(attn_mma,
        cudaFuncAttributeMaxDynamicSharedMemorySize, ASMEM);

    dim3 cb(32, 8), cg(DH / 32, DH / 32, 6);
    convert_weight6<<<cg, cb>>>(Wq, Wk, Wv, Wo, W1, W2, Wh, Wl);
    split_act<<<(TOKS * DH) / (256 * 4), 256>>>(hidden, hh, hl);

    size_t WW = (size_t)DH * DH;
    dim3 gg(DH / 80, TOKS / 128);   // (20, 16) = 320 CTAs, single wave @3/SM

    hgemm_v6<<<gg, 128, GSMEM>>>(hh, hl, Wh + 0 * WW, Wl + 0 * WW, bq,
                                 nullptr, qh, ql, 0, 1);
    hgemm_v6<<<gg, 128, GSMEM>>>(hh, hl, Wh + 1 * WW, Wl + 1 * WW, bk,
                                 nullptr, kh, kl, 0, 1);
    hgemm_v6<<<gg, 128, GSMEM>>>(hh, hl, Wh + 2 * WW, Wl + 2 * WW, bv,
                                 nullptr, vh, vl, 0, 1);

    dim3 ag(BATCH * NHEADS, SEQ / 64);   // (200, 8)
    attn_mma<<<ag, 128, ASMEM>>>(qh, ql, kh, kl, vh, vl, rke, rve, rm, ch, cl);

    hgemm_v6<<<gg, 128, GSMEM>>>(ch, cl, Wh + 3 * WW, Wl + 3 * WW, bo,
                                 nullptr, ah, al, 0, 1);
    hgemm_v6<<<gg, 128, GSMEM>>>(ah, al, Wh + 4 * WW, Wl + 4 * WW, b1,
                                 nullptr, h1h, h1l, 1, 1);
    hgemm_v6<<<gg, 128, GSMEM>>>(h1h, h1l, Wh + 5 * WW, Wl + 5 * WW, b2,
                                 out, nullptr, nullptr, 0, 0);
}